// round 8
// baseline (speedup 1.0000x reference)
#include <cuda_runtime.h>

#define B_   256
#define IN_  256
#define OUT_ 512
#define EPS_ 1e-7f

__device__ float g_relx[IN_ * OUT_];   // rel_x[i][o]

// ---------------------------------------------------------------------------
// Kernel 1: rel_x[i,o] = (sum_b min(t[b,o]/(x[b,i]+eps),1)) / colsum[i]
// Tile 32i x 32o, 256 thr, 2i x 2o per thread. Grid (8,16)=128 blocks.
// Recips computed at staging; raw x staged too so warp 0 accumulates the
// exact sequential-b colsum from smem, overlapped with the min-sum loop.
// ---------------------------------------------------------------------------
__global__ void k_relx(const float* __restrict__ x, const float* __restrict__ t) {
    __shared__ float Rs[128][32];   // [b][i_local] reciprocals
    __shared__ float Xr[128][32];   // [b][i_local] raw x (for colsum)
    __shared__ float Ts[128][32];   // [b][o_local]
    __shared__ float s_cs[32];

    const int i0  = blockIdx.x * 32;
    const int o0  = blockIdx.y * 32;
    const int lid = threadIdx.x;
    const int tp  = lid & 15;    // i pair: 2tp, 2tp+1
    const int to  = lid >> 4;    // o pair: 2to, 2to+1

    float acc00 = 0.f, acc01 = 0.f, acc10 = 0.f, acc11 = 0.f;
    float cs = 0.f;              // colsum carry (threads 0..31 only)

    for (int bb = 0; bb < B_; bb += 128) {
        #pragma unroll
        for (int k = 0; k < 4; k++) {
            int e   = lid + k * 256;
            int row = e >> 3;
            int c4  = (e & 7) * 4;
            float4 xv = *(const float4*)&x[(bb + row) * IN_ + i0 + c4];
            *(float4*)&Xr[row][c4] = xv;
            float4 rv;
            rv.x = 1.0f / (xv.x + EPS_);
            rv.y = 1.0f / (xv.y + EPS_);
            rv.z = 1.0f / (xv.z + EPS_);
            rv.w = 1.0f / (xv.w + EPS_);
            *(float4*)&Rs[row][c4] = rv;
        }
        #pragma unroll
        for (int k = 0; k < 4; k++) {
            int e   = lid + k * 256;
            int row = e >> 3;
            int c4  = (e & 7) * 4;
            *(float4*)&Ts[row][c4] = *(const float4*)&t[(bb + row) * OUT_ + o0 + c4];
        }
        __syncthreads();

        // Warp 0: exact sequential-b colsum from smem (ascending b, carried)
        if (lid < 32) {
            #pragma unroll 16
            for (int b = 0; b < 128; b++) cs += Xr[b][lid];
        }

        #pragma unroll 8
        for (int b = 0; b < 128; b++) {
            float2 r  = *(const float2*)&Rs[b][2 * tp];
            float2 tt = *(const float2*)&Ts[b][2 * to];
            acc00 += fminf(tt.x * r.x, 1.0f);
            acc01 += fminf(tt.y * r.x, 1.0f);
            acc10 += fminf(tt.x * r.y, 1.0f);
            acc11 += fminf(tt.y * r.y, 1.0f);
        }
        __syncthreads();
    }

    if (lid < 32) s_cs[lid] = cs;
    __syncthreads();

    const int i_0 = i0 + 2 * tp, i_1 = i_0 + 1;
    const int o_0 = o0 + 2 * to, o_1 = o_0 + 1;
    float cs0 = s_cs[2 * tp];
    float cs1 = s_cs[2 * tp + 1];
    g_relx[i_0 * OUT_ + o_0] = acc00 / cs0;
    g_relx[i_0 * OUT_ + o_1] = acc01 / cs0;
    g_relx[i_1 * OUT_ + o_0] = acc10 / cs1;
    g_relx[i_1 * OUT_ + o_1] = acc11 / cs1;
}

// ---------------------------------------------------------------------------
// Kernel 2: per-block w-argmax (exact first-max) + argmax_i x[b,i]*relx[i,o]
// with fmax-only inner loop, chunk-of-32 tracking, in-smem rescan.
// Tile 32b x 32o, 256 thr, 2b x 2o per thread. Grid (8,16)=128 blocks.
// Xs kept untransposed [b][i]: conflict-free float4 staging; b-reads are
// warp broadcasts.
// ---------------------------------------------------------------------------
__global__ void k_argmax(const float* __restrict__ x,
                         const float* __restrict__ w,
                         float* __restrict__ outx,
                         float* __restrict__ outw) {
    __shared__ float Xs[32][128];   // [b_local][i] x half... full 128-i half staged per pass
    __shared__ float Rl[128][32];   // [i][o_local]
    __shared__ float sv[8][32];
    __shared__ int   si[8][32];
    __shared__ float s_wv[32];
    __shared__ int   s_iw[32];

    const int b0  = blockIdx.x * 32;
    const int o0  = blockIdx.y * 32;
    const int lid = threadIdx.x;
    const int tb  = lid & 15;    // b pair: 2tb, 2tb+1
    const int to  = lid >> 4;    // o pair: 2to, 2to+1

    // --- w-argmax for this block's 32 o's: thread (ic, ol) scans 32 i's ---
    {
        const int ol = lid & 31;
        const int ic = lid >> 5;
        const int o  = o0 + ol;
        float best = -1.f;
        int   bi   = 0;
        #pragma unroll
        for (int j = 0; j < 32; j++) {
            int i = ic * 32 + j;
            float v = w[i * OUT_ + o];
            if (v > best) { best = v; bi = i; }
        }
        sv[ic][ol] = best;
        si[ic][ol] = bi;
    }
    __syncthreads();
    if (lid < 32) {
        float bv = sv[0][lid];
        int   ix = si[0][lid];
        #pragma unroll
        for (int c = 1; c < 8; c++)
            if (sv[c][lid] > bv) { bv = sv[c][lid]; ix = si[c][lid]; }
        s_wv[lid] = bv;
        s_iw[lid] = ix;
    }

    // --- main argmax: 2 halves of 128 i each ---
    float best00 = -1.f, best01 = -1.f, best10 = -1.f, best11 = -1.f;
    int   bc00 = 0, bc01 = 0, bc10 = 0, bc11 = 0;
    int   id00 = 0, id01 = 0, id10 = 0, id11 = 0;

    for (int half = 0; half < 2; half++) {
        const int iz = half * 128;
        #pragma unroll
        for (int k = 0; k < 4; k++) {       // Xs: [32 b][128 i], float4 coalesced
            int e   = lid + k * 256;
            int row = e >> 5;               // b-local
            int c4  = (e & 31) * 4;         // i-local
            *(float4*)&Xs[row][c4] = *(const float4*)&x[(b0 + row) * IN_ + iz + c4];
        }
        #pragma unroll
        for (int k = 0; k < 4; k++) {       // Rl: [128 i][32 o]
            int e   = lid + k * 256;
            int row = e >> 3;
            int c4  = (e & 7) * 4;
            *(float4*)&Rl[row][c4] = *(const float4*)&g_relx[(iz + row) * OUT_ + o0 + c4];
        }
        __syncthreads();

        #pragma unroll
        for (int c = 0; c < 4; c++) {
            float cm00 = -1.f, cm01 = -1.f, cm10 = -1.f, cm11 = -1.f;
            #pragma unroll
            for (int j = 0; j < 32; j++) {
                int i = c * 32 + j;
                float  xa = Xs[2 * tb][i];
                float  xb = Xs[2 * tb + 1][i];
                float2 rv = *(const float2*)&Rl[i][2 * to];
                cm00 = fmaxf(cm00, xa * rv.x);
                cm01 = fmaxf(cm01, xa * rv.y);
                cm10 = fmaxf(cm10, xb * rv.x);
                cm11 = fmaxf(cm11, xb * rv.y);
            }
            const int cb = iz + c * 32;
            if (cm00 > best00) { best00 = cm00; bc00 = cb; }
            if (cm01 > best01) { best01 = cm01; bc01 = cb; }
            if (cm10 > best10) { best10 = cm10; bc10 = cb; }
            if (cm11 > best11) { best11 = cm11; bc11 = cb; }
        }

        // In-smem rescans (descending j, == overwrite -> exact first index)
        if (bc00 >= iz) {
            const int cl = bc00 - iz;
            #pragma unroll 8
            for (int j = 31; j >= 0; j--)
                if (Xs[2 * tb][cl + j] * Rl[cl + j][2 * to] == best00) id00 = bc00 + j;
        }
        if (bc01 >= iz) {
            const int cl = bc01 - iz;
            #pragma unroll 8
            for (int j = 31; j >= 0; j--)
                if (Xs[2 * tb][cl + j] * Rl[cl + j][2 * to + 1] == best01) id01 = bc01 + j;
        }
        if (bc10 >= iz) {
            const int cl = bc10 - iz;
            #pragma unroll 8
            for (int j = 31; j >= 0; j--)
                if (Xs[2 * tb + 1][cl + j] * Rl[cl + j][2 * to] == best10) id10 = bc10 + j;
        }
        if (bc11 >= iz) {
            const int cl = bc11 - iz;
            #pragma unroll 8
            for (int j = 31; j >= 0; j--)
                if (Xs[2 * tb + 1][cl + j] * Rl[cl + j][2 * to + 1] == best11) id11 = bc11 + j;
        }
        __syncthreads();
    }

    const int b_0 = b0 + 2 * tb, b_1 = b_0 + 1;
    const int o_0 = o0 + 2 * to;

    float2 ox0, ox1;
    ox0.x = x[b_0 * IN_ + id00] * w[id00 * OUT_ + o_0];
    ox0.y = x[b_0 * IN_ + id01] * w[id01 * OUT_ + o_0 + 1];
    ox1.x = x[b_1 * IN_ + id10] * w[id10 * OUT_ + o_0];
    ox1.y = x[b_1 * IN_ + id11] * w[id11 * OUT_ + o_0 + 1];
    *(float2*)&outx[b_0 * OUT_ + o_0] = ox0;
    *(float2*)&outx[b_1 * OUT_ + o_0] = ox1;

    const int lo0 = 2 * to, lo1 = 2 * to + 1;
    const int iw0 = s_iw[lo0], iw1 = s_iw[lo1];
    const float wv0 = s_wv[lo0], wv1 = s_wv[lo1];
    float2 ow0, ow1;
    ow0.x = x[b_0 * IN_ + iw0] * wv0;
    ow0.y = x[b_0 * IN_ + iw1] * wv1;
    ow1.x = x[b_1 * IN_ + iw0] * wv0;
    ow1.y = x[b_1 * IN_ + iw1] * wv1;
    *(float2*)&outw[b_0 * OUT_ + o_0] = ow0;
    *(float2*)&outw[b_1 * OUT_ + o_0] = ow1;
}

// ---------------------------------------------------------------------------
extern "C" void kernel_launch(void* const* d_in, const int* in_sizes, int n_in,
                              void* d_out, int out_size) {
    const float* x = (const float*)d_in[0];
    const float* w = (const float*)d_in[1];
    const float* t = (const float*)d_in[2];
    float* outx = (float*)d_out;
    float* outw = (float*)d_out + B_ * OUT_;

    k_relx  <<<dim3(IN_ / 32, OUT_ / 32), 256>>>(x, t);
    k_argmax<<<dim3(B_  / 32, OUT_ / 32), 256>>>(x, w, outx, outw);
}

// round 9
// speedup vs baseline: 1.9835x; 1.9835x over previous
#include <cuda_runtime.h>

#define B_   256
#define IN_  256
#define OUT_ 512
#define EPS_ 1e-7f

__device__ float g_relx[IN_ * OUT_];   // rel_x[i][o]

// ---------------------------------------------------------------------------
// Kernel 1: rel_x[i,o] = (sum_b min(t[b,o]/(x[b,i]+eps),1)) / colsum[i]
// Tile 32i x 32o, 256 thr, 2i x 2o per thread (float2), grid (8,16)=128.
// Recips inline at staging. Colsum: parallel 8x32 partials from global
// (ascending-b chunks), reduced by warp 0.
// ---------------------------------------------------------------------------
__global__ void k_relx(const float* __restrict__ x, const float* __restrict__ t) {
    __shared__ float Rs[128][32];   // [b][i_local] reciprocals
    __shared__ float Ts[128][32];   // [b][o_local]
    __shared__ float ps[8][32];     // colsum partials
    __shared__ float s_cs[32];

    const int i0  = blockIdx.x * 32;
    const int o0  = blockIdx.y * 32;
    const int lid = threadIdx.x;
    const int tp  = lid & 15;    // i pair: 2tp, 2tp+1
    const int to  = lid >> 4;    // o pair: 2to, 2to+1

    // Parallel colsum: thread (seg, il) sums 32 consecutive b's for column i0+il
    {
        const int il  = lid & 31;
        const int seg = lid >> 5;
        float s = 0.0f;
        #pragma unroll
        for (int j = 0; j < 32; j++)
            s += x[(seg * 32 + j) * IN_ + i0 + il];
        ps[seg][il] = s;
    }

    float acc00 = 0.f, acc01 = 0.f, acc10 = 0.f, acc11 = 0.f;

    for (int bb = 0; bb < B_; bb += 128) {
        #pragma unroll
        for (int k = 0; k < 4; k++) {
            int e   = lid + k * 256;
            int row = e >> 3;
            int c4  = (e & 7) * 4;
            float4 xv = *(const float4*)&x[(bb + row) * IN_ + i0 + c4];
            float4 rv;
            rv.x = 1.0f / (xv.x + EPS_);
            rv.y = 1.0f / (xv.y + EPS_);
            rv.z = 1.0f / (xv.z + EPS_);
            rv.w = 1.0f / (xv.w + EPS_);
            *(float4*)&Rs[row][c4] = rv;
            *(float4*)&Ts[row][c4] = *(const float4*)&t[(bb + row) * OUT_ + o0 + c4];
        }
        __syncthreads();

        if (bb == 0 && lid < 32) {           // reduce colsum partials once
            float s = ps[0][lid];
            #pragma unroll
            for (int c = 1; c < 8; c++) s += ps[c][lid];
            s_cs[lid] = s;
        }

        #pragma unroll 8
        for (int b = 0; b < 128; b++) {
            float2 r  = *(const float2*)&Rs[b][2 * tp];
            float2 tt = *(const float2*)&Ts[b][2 * to];
            acc00 += fminf(tt.x * r.x, 1.0f);
            acc01 += fminf(tt.y * r.x, 1.0f);
            acc10 += fminf(tt.x * r.y, 1.0f);
            acc11 += fminf(tt.y * r.y, 1.0f);
        }
        __syncthreads();
    }

    const int i_0 = i0 + 2 * tp, i_1 = i_0 + 1;
    const int o_0 = o0 + 2 * to, o_1 = o_0 + 1;
    float cs0 = s_cs[2 * tp];
    float cs1 = s_cs[2 * tp + 1];
    g_relx[i_0 * OUT_ + o_0] = acc00 / cs0;
    g_relx[i_0 * OUT_ + o_1] = acc01 / cs0;
    g_relx[i_1 * OUT_ + o_0] = acc10 / cs1;
    g_relx[i_1 * OUT_ + o_1] = acc11 / cs1;
}

// ---------------------------------------------------------------------------
// Kernel 2: w-argmax prologue + argmax_i x[b,i]*relx[i,o] with fmax-only
// inner loop (conflict-free Xs[128][34]/Rl[128][32] layouts), chunk-of-32
// tracking, in-smem rescan (first-max exact). Direct outputs.
// Tile 32b x 32o, 256 thr, 2b x 2o per thread. Grid (8,16)=128 blocks.
// ---------------------------------------------------------------------------
__global__ void k_argmax(const float* __restrict__ x,
                         const float* __restrict__ w,
                         float* __restrict__ outx,
                         float* __restrict__ outw) {
    __shared__ float Xs[128][34];   // [i][b_local] transposed, padded
    __shared__ float Rl[128][32];   // [i][o_local]
    __shared__ float sv[8][32];
    __shared__ int   si[8][32];
    __shared__ float s_wv[32];
    __shared__ int   s_iw[32];

    const int b0  = blockIdx.x * 32;
    const int o0  = blockIdx.y * 32;
    const int lid = threadIdx.x;
    const int tb  = lid & 15;    // b pair: 2tb, 2tb+1
    const int to  = lid >> 4;    // o pair: 2to, 2to+1

    // --- w-argmax for this block's 32 o's: thread (ic, ol) scans 32 i's ---
    {
        const int ol = lid & 31;
        const int ic = lid >> 5;
        const int o  = o0 + ol;
        float best = -1.f;
        int   bi   = 0;
        #pragma unroll
        for (int j = 0; j < 32; j++) {
            int i = ic * 32 + j;
            float v = w[i * OUT_ + o];
            if (v > best) { best = v; bi = i; }
        }
        sv[ic][ol] = best;
        si[ic][ol] = bi;
    }
    __syncthreads();
    if (lid < 32) {
        float bv = sv[0][lid];
        int   ix = si[0][lid];
        #pragma unroll
        for (int c = 1; c < 8; c++)
            if (sv[c][lid] > bv) { bv = sv[c][lid]; ix = si[c][lid]; }
        s_wv[lid] = bv;
        s_iw[lid] = ix;
    }

    // --- main argmax: 2 halves of 128 i ---
    float best00 = -1.f, best01 = -1.f, best10 = -1.f, best11 = -1.f;
    int   bc00 = 0, bc01 = 0, bc10 = 0, bc11 = 0;
    int   id00 = 0, id01 = 0, id10 = 0, id11 = 0;

    for (int half = 0; half < 2; half++) {
        const int iz = half * 128;
        #pragma unroll
        for (int k = 0; k < 2; k++) {       // Xs transposed: [i][b], 32 b rows
            int e   = lid + k * 256;        // 0..511
            int row = e >> 5;               // b-local 0..15  (k=1: 8..15)
            int c4  = (e & 31) * 4;         // i-local 0..124
            float4 v0 = *(const float4*)&x[(b0 + 2 * row)     * IN_ + iz + c4];
            float4 v1 = *(const float4*)&x[(b0 + 2 * row + 1) * IN_ + iz + c4];
            Xs[c4 + 0][2 * row] = v0.x;  Xs[c4 + 0][2 * row + 1] = v1.x;
            Xs[c4 + 1][2 * row] = v0.y;  Xs[c4 + 1][2 * row + 1] = v1.y;
            Xs[c4 + 2][2 * row] = v0.z;  Xs[c4 + 2][2 * row + 1] = v1.z;
            Xs[c4 + 3][2 * row] = v0.w;  Xs[c4 + 3][2 * row + 1] = v1.w;
        }
        #pragma unroll
        for (int k = 0; k < 4; k++) {       // Rl: [i][o]
            int e   = lid + k * 256;
            int row = e >> 3;
            int c4  = (e & 7) * 4;
            *(float4*)&Rl[row][c4] = *(const float4*)&g_relx[(iz + row) * OUT_ + o0 + c4];
        }
        __syncthreads();

        #pragma unroll
        for (int c = 0; c < 4; c++) {
            float cm00 = -1.f, cm01 = -1.f, cm10 = -1.f, cm11 = -1.f;
            #pragma unroll
            for (int j = 0; j < 32; j++) {
                int i = c * 32 + j;
                float2 xv = *(const float2*)&Xs[i][2 * tb];
                float2 rv = *(const float2*)&Rl[i][2 * to];
                cm00 = fmaxf(cm00, xv.x * rv.x);
                cm01 = fmaxf(cm01, xv.x * rv.y);
                cm10 = fmaxf(cm10, xv.y * rv.x);
                cm11 = fmaxf(cm11, xv.y * rv.y);
            }
            const int cb = iz + c * 32;
            if (cm00 > best00) { best00 = cm00; bc00 = cb; }
            if (cm01 > best01) { best01 = cm01; bc01 = cb; }
            if (cm10 > best10) { best10 = cm10; bc10 = cb; }
            if (cm11 > best11) { best11 = cm11; bc11 = cb; }
        }

        // In-smem rescans (descending j, == overwrite -> exact first index)
        if (bc00 >= iz) {
            const int cl = bc00 - iz;
            #pragma unroll 8
            for (int j = 31; j >= 0; j--)
                if (Xs[cl + j][2 * tb] * Rl[cl + j][2 * to] == best00) id00 = bc00 + j;
        }
        if (bc01 >= iz) {
            const int cl = bc01 - iz;
            #pragma unroll 8
            for (int j = 31; j >= 0; j--)
                if (Xs[cl + j][2 * tb] * Rl[cl + j][2 * to + 1] == best01) id01 = bc01 + j;
        }
        if (bc10 >= iz) {
            const int cl = bc10 - iz;
            #pragma unroll 8
            for (int j = 31; j >= 0; j--)
                if (Xs[cl + j][2 * tb + 1] * Rl[cl + j][2 * to] == best10) id10 = bc10 + j;
        }
        if (bc11 >= iz) {
            const int cl = bc11 - iz;
            #pragma unroll 8
            for (int j = 31; j >= 0; j--)
                if (Xs[cl + j][2 * tb + 1] * Rl[cl + j][2 * to + 1] == best11) id11 = bc11 + j;
        }
        __syncthreads();
    }

    const int b_0 = b0 + 2 * tb, b_1 = b_0 + 1;
    const int o_0 = o0 + 2 * to;

    float2 ox0, ox1;
    ox0.x = x[b_0 * IN_ + id00] * w[id00 * OUT_ + o_0];
    ox0.y = x[b_0 * IN_ + id01] * w[id01 * OUT_ + o_0 + 1];
    ox1.x = x[b_1 * IN_ + id10] * w[id10 * OUT_ + o_0];
    ox1.y = x[b_1 * IN_ + id11] * w[id11 * OUT_ + o_0 + 1];
    *(float2*)&outx[b_0 * OUT_ + o_0] = ox0;
    *(float2*)&outx[b_1 * OUT_ + o_0] = ox1;

    const int lo0 = 2 * to, lo1 = 2 * to + 1;
    const int iw0 = s_iw[lo0], iw1 = s_iw[lo1];
    const float wv0 = s_wv[lo0], wv1 = s_wv[lo1];
    float2 ow0, ow1;
    ow0.x = x[b_0 * IN_ + iw0] * wv0;
    ow0.y = x[b_0 * IN_ + iw1] * wv1;
    ow1.x = x[b_1 * IN_ + iw0] * wv0;
    ow1.y = x[b_1 * IN_ + iw1] * wv1;
    *(float2*)&outw[b_0 * OUT_ + o_0] = ow0;
    *(float2*)&outw[b_1 * OUT_ + o_0] = ow1;
}

// ---------------------------------------------------------------------------
extern "C" void kernel_launch(void* const* d_in, const int* in_sizes, int n_in,
                              void* d_out, int out_size) {
    const float* x = (const float*)d_in[0];
    const float* w = (const float*)d_in[1];
    const float* t = (const float*)d_in[2];
    float* outx = (float*)d_out;
    float* outw = (float*)d_out + B_ * OUT_;

    k_relx  <<<dim3(IN_ / 32, OUT_ / 32), 256>>>(x, t);
    k_argmax<<<dim3(B_  / 32, OUT_ / 32), 256>>>(x, w, outx, outw);
}

// round 10
// speedup vs baseline: 2.1239x; 1.0708x over previous
#include <cuda_runtime.h>

#define B_   256
#define IN_  256
#define OUT_ 512
#define EPS_ 1e-7f

__device__ float g_relx[IN_ * OUT_];   // rel_x[i][o]

// ---------------------------------------------------------------------------
// Kernel 1: rel_x[i,o] = (sum_b min(t[b,o]/(x[b,i]+eps),1)) / colsum[i]
// Tile 32i x 16o, 256 thr (o fastest), 2i x 1o per thread. Grid (8,32)=256.
// Recips inline at staging. Colsum: parallel 8x32 partials (ascending-b
// chunks) reduced once.
// ---------------------------------------------------------------------------
__global__ void k_relx(const float* __restrict__ x, const float* __restrict__ t) {
    __shared__ float Rs[128][32];   // [b][i_local] reciprocals
    __shared__ float Ts[128][16];   // [b][o_local]
    __shared__ float ps[8][32];     // colsum partials
    __shared__ float s_cs[32];

    const int i0  = blockIdx.x * 32;
    const int o0  = blockIdx.y * 16;
    const int lid = threadIdx.x;
    const int to  = lid & 15;    // o
    const int tp  = lid >> 4;    // i pair: 2tp, 2tp+1

    // Parallel colsum partials: thread (seg, il) sums 32 consecutive b's
    {
        const int il  = lid & 31;
        const int seg = lid >> 5;
        float s = 0.0f;
        #pragma unroll
        for (int j = 0; j < 32; j++)
            s += x[(seg * 32 + j) * IN_ + i0 + il];
        ps[seg][il] = s;
    }

    float acc0 = 0.f, acc1 = 0.f;

    for (int bb = 0; bb < B_; bb += 128) {
        #pragma unroll
        for (int k = 0; k < 4; k++) {       // Rs: 4096 floats
            int e   = lid + k * 256;
            int row = e >> 3;
            int c4  = (e & 7) * 4;
            float4 xv = *(const float4*)&x[(bb + row) * IN_ + i0 + c4];
            float4 rv;
            rv.x = 1.0f / (xv.x + EPS_);
            rv.y = 1.0f / (xv.y + EPS_);
            rv.z = 1.0f / (xv.z + EPS_);
            rv.w = 1.0f / (xv.w + EPS_);
            *(float4*)&Rs[row][c4] = rv;
        }
        #pragma unroll
        for (int k = 0; k < 2; k++) {       // Ts: 2048 floats
            int e   = lid + k * 256;
            int row = e >> 2;
            int c4  = (e & 3) * 4;
            *(float4*)&Ts[row][c4] = *(const float4*)&t[(bb + row) * OUT_ + o0 + c4];
        }
        __syncthreads();

        if (bb == 0 && lid < 32) {          // reduce colsum partials once
            float s = ps[0][lid];
            #pragma unroll
            for (int c = 1; c < 8; c++) s += ps[c][lid];
            s_cs[lid] = s;
        }

        #pragma unroll 8
        for (int b = 0; b < 128; b++) {
            float2 r  = *(const float2*)&Rs[b][2 * tp];
            float  tv = Ts[b][to];
            acc0 += fminf(tv * r.x, 1.0f);
            acc1 += fminf(tv * r.y, 1.0f);
        }
        __syncthreads();
    }

    const int i_0 = i0 + 2 * tp, i_1 = i_0 + 1;
    const int o   = o0 + to;
    g_relx[i_0 * OUT_ + o] = acc0 / s_cs[2 * tp];
    g_relx[i_1 * OUT_ + o] = acc1 / s_cs[2 * tp + 1];
}

// ---------------------------------------------------------------------------
// Kernel 2: w-argmax prologue + argmax_i x[b,i]*relx[i,o], fmax-only inner
// loop, chunk-of-32 tracking, in-smem rescan (exact first-max), direct
// outputs. Tile 16b x 32o, 256 thr (o fastest), 1b x 2o per thread.
// Grid (16,16)=256 blocks.
// Xs row-major [b][i] (stride 132): conflict-free float4 staging; inner
// x-reads are warp broadcasts (2 distinct tb per warp).
// ---------------------------------------------------------------------------
__global__ void k_argmax(const float* __restrict__ x,
                         const float* __restrict__ w,
                         float* __restrict__ outx,
                         float* __restrict__ outw) {
    __shared__ float Xs[16][132];   // [b_local][i] half-tile (128 i + pad)
    __shared__ float Rl[128][32];   // [i][o_local]
    __shared__ float sv[8][32];
    __shared__ int   si[8][32];
    __shared__ float s_wv[32];
    __shared__ int   s_iw[32];

    const int b0  = blockIdx.x * 16;
    const int o0  = blockIdx.y * 32;
    const int lid = threadIdx.x;
    const int to  = lid & 15;    // o pair: 2to, 2to+1
    const int tb  = lid >> 4;    // b: 0..15

    // --- w-argmax for this block's 32 o's: thread (ic, ol) scans 32 i's ---
    {
        const int ol = lid & 31;
        const int ic = lid >> 5;
        const int o  = o0 + ol;
        float best = -1.f;
        int   bi   = 0;
        #pragma unroll
        for (int j = 0; j < 32; j++) {
            int i = ic * 32 + j;
            float v = w[i * OUT_ + o];
            if (v > best) { best = v; bi = i; }
        }
        sv[ic][ol] = best;
        si[ic][ol] = bi;
    }
    __syncthreads();
    if (lid < 32) {
        float bv = sv[0][lid];
        int   ix = si[0][lid];
        #pragma unroll
        for (int c = 1; c < 8; c++)
            if (sv[c][lid] > bv) { bv = sv[c][lid]; ix = si[c][lid]; }
        s_wv[lid] = bv;
        s_iw[lid] = ix;
    }

    // --- main argmax: 2 halves of 128 i ---
    float best0 = -1.f, best1 = -1.f;
    int   bc0 = 0, bc1 = 0;
    int   id0 = 0, id1 = 0;

    for (int half = 0; half < 2; half++) {
        const int iz = half * 128;
        #pragma unroll
        for (int k = 0; k < 2; k++) {       // Xs: [16 b][128 i], float4 rows
            int e   = lid + k * 256;        // 0..511
            int row = e >> 5;               // b-local 0..15
            int c4  = (e & 31) * 4;         // i-local 0..124
            *(float4*)&Xs[row][c4] = *(const float4*)&x[(b0 + row) * IN_ + iz + c4];
        }
        #pragma unroll
        for (int k = 0; k < 4; k++) {       // Rl: [128 i][32 o]
            int e   = lid + k * 256;
            int row = e >> 3;
            int c4  = (e & 7) * 4;
            *(float4*)&Rl[row][c4] = *(const float4*)&g_relx[(iz + row) * OUT_ + o0 + c4];
        }
        __syncthreads();

        #pragma unroll
        for (int c = 0; c < 4; c++) {
            float cm0 = -1.f, cm1 = -1.f;
            #pragma unroll
            for (int j = 0; j < 32; j++) {
                int i = c * 32 + j;
                float  xv = Xs[tb][i];
                float2 rv = *(const float2*)&Rl[i][2 * to];
                cm0 = fmaxf(cm0, xv * rv.x);
                cm1 = fmaxf(cm1, xv * rv.y);
            }
            const int cb = iz + c * 32;
            if (cm0 > best0) { best0 = cm0; bc0 = cb; }
            if (cm1 > best1) { best1 = cm1; bc1 = cb; }
        }

        // In-smem rescans (descending j, == overwrite -> exact first index)
        if (bc0 >= iz) {
            const int cl = bc0 - iz;
            #pragma unroll 8
            for (int j = 31; j >= 0; j--)
                if (Xs[tb][cl + j] * Rl[cl + j][2 * to] == best0) id0 = bc0 + j;
        }
        if (bc1 >= iz) {
            const int cl = bc1 - iz;
            #pragma unroll 8
            for (int j = 31; j >= 0; j--)
                if (Xs[tb][cl + j] * Rl[cl + j][2 * to + 1] == best1) id1 = bc1 + j;
        }
        __syncthreads();
    }

    const int b  = b0 + tb;
    const int o_ = o0 + 2 * to;

    float2 ox;
    ox.x = x[b * IN_ + id0] * w[id0 * OUT_ + o_];
    ox.y = x[b * IN_ + id1] * w[id1 * OUT_ + o_ + 1];
    *(float2*)&outx[b * OUT_ + o_] = ox;

    const int lo0 = 2 * to, lo1 = 2 * to + 1;
    float2 ow;
    ow.x = x[b * IN_ + s_iw[lo0]] * s_wv[lo0];
    ow.y = x[b * IN_ + s_iw[lo1]] * s_wv[lo1];
    *(float2*)&outw[b * OUT_ + o_] = ow;
}

// ---------------------------------------------------------------------------
extern "C" void kernel_launch(void* const* d_in, const int* in_sizes, int n_in,
                              void* d_out, int out_size) {
    const float* x = (const float*)d_in[0];
    const float* w = (const float*)d_in[1];
    const float* t = (const float*)d_in[2];
    float* outx = (float*)d_out;
    float* outw = (float*)d_out + B_ * OUT_;

    k_relx  <<<dim3(IN_ / 32, OUT_ / 16), 256>>>(x, t);
    k_argmax<<<dim3(B_  / 16, OUT_ / 32), 256>>>(x, w, outx, outw);
}